// round 12
// baseline (speedup 1.0000x reference)
#include <cuda_runtime.h>

#define NODES 100000
#define NEDGES 3200000
#define DD 20
#define BCAP 128   // bucket capacity per node; P(in-deg > 128) ~ 0 (Poisson mean 32)
#define GSTR 32    // padded row stride (floats): 128B-aligned rows, 1 L1 line/gather

// ---------------- static device scratch (no allocations allowed) ----------------
__device__ int   d_cnt[2 * NODES];         // [0:N) in-deg (bucket fill), [N:2N) out-deg
__device__ int   d_col[NODES * BCAP];      // bucket CSR: node n's srcs at [n*BCAP, n*BCAP+cnt)
__device__ float d_din[NODES];
__device__ float d_dout[NODES];
__device__ float d_g0[NODES];
__device__ __align__(128) float d_gA[NODES * GSTR];   // activations g = h*dout (padded)
__device__ __align__(128) float d_gB[NODES * GSTR];
__device__ __align__(128) float d_y[NODES * GSTR];    // y = g @ W (padded)

// ---------------- graph build: single scatter pass (no hist, no scan) ----------
__global__ void k_scatter(const int* __restrict__ src, const int* __restrict__ dst) {
    int e = blockIdx.x * blockDim.x + threadIdx.x;
    if (e < NEDGES) {
        int s = src[e], d = dst[e];
        int p = atomicAdd(&d_cnt[d], 1);
        d_col[d * BCAP + p] = s;
        atomicAdd(&d_cnt[NODES + s], 1);   // out-degree count
    }
}

__global__ void k_init(const float* __restrict__ feat) {
    int i = blockIdx.x * blockDim.x + threadIdx.x;
    if (i < NODES) {
        float di = rsqrtf((float)(d_cnt[i] + 1));           // +1 self-loop
        float dq = rsqrtf((float)(d_cnt[NODES + i] + 1));
        d_din[i]  = di;
        d_dout[i] = dq;
        d_g0[i]   = feat[i] * dq;                           // layer-0 source values
    }
}

// ---------------- layer 0 : scalar aggregation, D_in = 1 ----------------
__global__ void __launch_bounds__(256)
k_layer0(const float* __restrict__ W, const float* __restrict__ b) {
    const unsigned FULL = 0xffffffffu;
    int lane = threadIdx.x & 31;
    int w    = (blockIdx.x * blockDim.x + threadIdx.x) >> 5;
    int nw   = (gridDim.x * blockDim.x) >> 5;
    int tt   = lane < DD ? lane : 0;
    float wt = W[tt];
    float bt = b[tt];
    for (int n = w; n < NODES; n += nw) {
        int beg = n * BCAP, end = beg + d_cnt[n];
        float acc = (lane == 0) ? d_g0[n] : 0.f;     // self-loop
        for (int j = beg + lane; j < end; j += 32)
            acc += __ldg(&d_g0[__ldg(&d_col[j])]);
        #pragma unroll
        for (int off = 16; off; off >>= 1)
            acc += __shfl_xor_sync(FULL, acc, off);
        if (lane < DD) {
            float r = fmaf(d_din[n] * acc, wt, bt);
            r = fmaxf(r, 0.f);
            d_gA[n * GSTR + lane] = r * d_dout[n];   // g = h*dout (padded row)
        }
    }
}

// ---------------- dense pre-multiply: y = g @ W (per node, 20x20) -------------
__global__ void __launch_bounds__(256)
k_dense(const float* __restrict__ gin, float* __restrict__ yout,
        const float* __restrict__ W) {
    __shared__ float Wsm[DD * DD];
    for (int i = threadIdx.x; i < DD * DD; i += blockDim.x) Wsm[i] = W[i];
    __syncthreads();

    int n = blockIdx.x * blockDim.x + threadIdx.x;
    if (n >= NODES) return;

    const float4* grow = (const float4*)(gin + n * GSTR);
    float s[DD];
    #pragma unroll
    for (int q = 0; q < 5; q++) {
        float4 v = __ldg(&grow[q]);
        s[4 * q + 0] = v.x; s[4 * q + 1] = v.y; s[4 * q + 2] = v.z; s[4 * q + 3] = v.w;
    }
    float o[DD];
    #pragma unroll
    for (int k = 0; k < DD; k++) o[k] = 0.f;
    #pragma unroll
    for (int j = 0; j < DD; j++) {
        float sj = s[j];
        #pragma unroll
        for (int k = 0; k < DD; k++)
            o[k] = fmaf(sj, Wsm[j * DD + k], o[k]);
    }
    float4* yrow = (float4*)(yout + n * GSTR);
    #pragma unroll
    for (int q = 0; q < 5; q++) {
        float4 v;
        v.x = o[4 * q + 0]; v.y = o[4 * q + 1]; v.z = o[4 * q + 2]; v.w = o[4 * q + 3];
        yrow[q] = v;
    }
}

// ---------------- aggregation + elementwise epilogue ---------------------------
// s = A.y (gather); out = (relu(din*s + b)) * dout, applied componentwise on
// lanes 0-4's float4 accumulators. NO matvec, NO wcol, NO broadcast shfls.
template <int RELU, int SCALE, int PACKED>
__global__ void __launch_bounds__(256)
k_agg(const float* __restrict__ yin, float* __restrict__ gout,
      const float* __restrict__ b) {
    const unsigned FULL = 0xffffffffu;
    int lane = threadIdx.x & 31;
    int w    = (blockIdx.x * blockDim.x + threadIdx.x) >> 5;
    int nw   = (gridDim.x * blockDim.x) >> 5;
    // lane layout: 6 edges x 5 float4 chunks (lanes 30,31 idle in gather)
    int c    = lane % 5;
    int esub = lane / 5;
    bool lok = lane < 30;
    float4 bv = __ldg(&((const float4*)b)[c]);   // lane c holds b[4c..4c+3]
    const float4* yin4 = (const float4*)yin;     // 8 float4 per padded row

    for (int n = w; n < NODES; n += nw) {
        int beg = n * BCAP, end = beg + __ldg(&d_cnt[n]);
        float4 acc  = make_float4(0.f, 0.f, 0.f, 0.f);
        float4 acc2 = make_float4(0.f, 0.f, 0.f, 0.f);
        if (lok && esub == 0) acc = __ldg(&yin4[(n << 3) + c]);   // self-loop

        // ---- main loop: 24 edges / body, 4 rows in flight per lane ----
        int j0 = beg;
        if (lok) {
            for (; j0 + 24 <= end; j0 += 24) {
                int jj = j0 + esub;
                int s0 = __ldg(&d_col[jj]);
                int s1 = __ldg(&d_col[jj + 6]);
                int s2 = __ldg(&d_col[jj + 12]);
                int s3 = __ldg(&d_col[jj + 18]);
                float4 x0 = __ldg(&yin4[(s0 << 3) + c]);
                float4 x1 = __ldg(&yin4[(s1 << 3) + c]);
                float4 x2 = __ldg(&yin4[(s2 << 3) + c]);
                float4 x3 = __ldg(&yin4[(s3 << 3) + c]);
                acc.x  += x0.x; acc.y  += x0.y; acc.z  += x0.z; acc.w  += x0.w;
                acc2.x += x1.x; acc2.y += x1.y; acc2.z += x1.z; acc2.w += x1.w;
                acc.x  += x2.x; acc.y  += x2.y; acc.z  += x2.z; acc.w  += x2.w;
                acc2.x += x3.x; acc2.y += x3.y; acc2.z += x3.z; acc2.w += x3.w;
            }
        } else {
            j0 = end - ((end - beg) % 24);           // loop-exit-consistent for lanes 30,31
            if (j0 < beg) j0 = beg;
        }

        // ---- remainder: up to 23 edges, predicated ----
        #pragma unroll 2
        for (; j0 < end; j0 += 6) {
            int j = j0 + esub;
            if (lok && j < end) {
                int s = __ldg(&d_col[j]);
                float4 x = __ldg(&yin4[(s << 3) + c]);
                acc.x += x.x; acc.y += x.y; acc.z += x.z; acc.w += x.w;
            }
        }
        acc.x += acc2.x; acc.y += acc2.y; acc.z += acc2.z; acc.w += acc2.w;

        // Reduce the 6 edge groups (stride 5), predicated folds (no double count):
        float4 t;
        t.x = __shfl_down_sync(FULL, acc.x, 15);
        t.y = __shfl_down_sync(FULL, acc.y, 15);
        t.z = __shfl_down_sync(FULL, acc.z, 15);
        t.w = __shfl_down_sync(FULL, acc.w, 15);
        if (lane < 15) { acc.x += t.x; acc.y += t.y; acc.z += t.z; acc.w += t.w; }
        t.x = __shfl_down_sync(FULL, acc.x, 10);
        t.y = __shfl_down_sync(FULL, acc.y, 10);
        t.z = __shfl_down_sync(FULL, acc.z, 10);
        t.w = __shfl_down_sync(FULL, acc.w, 10);
        if (lane < 5) { acc.x += t.x; acc.y += t.y; acc.z += t.z; acc.w += t.w; }
        t.x = __shfl_down_sync(FULL, acc.x, 5);
        t.y = __shfl_down_sync(FULL, acc.y, 5);
        t.z = __shfl_down_sync(FULL, acc.z, 5);
        t.w = __shfl_down_sync(FULL, acc.w, 5);
        if (lane < 5) { acc.x += t.x; acc.y += t.y; acc.z += t.z; acc.w += t.w; }

        // Elementwise epilogue on lanes 0-4 (each holds s[4c..4c+3]):
        if (lane < 5) {
            float din = __ldg(&d_din[n]);
            float r0 = fmaf(din, acc.x, bv.x);
            float r1 = fmaf(din, acc.y, bv.y);
            float r2 = fmaf(din, acc.z, bv.z);
            float r3 = fmaf(din, acc.w, bv.w);
            if (RELU) {
                r0 = fmaxf(r0, 0.f); r1 = fmaxf(r1, 0.f);
                r2 = fmaxf(r2, 0.f); r3 = fmaxf(r3, 0.f);
            }
            if (SCALE) {
                float dq = __ldg(&d_dout[n]);
                r0 *= dq; r1 *= dq; r2 *= dq; r3 *= dq;
            }
            float4 v; v.x = r0; v.y = r1; v.z = r2; v.w = r3;
            if (PACKED) ((float4*)(gout + n * DD))[c] = v;    // final: packed fp32 rows
            else        ((float4*)(gout + n * GSTR))[c] = v;  // mids: padded rows
        }
    }
}

// ---------------- launch ----------------
#define L0GRID 1184
#define AGRID  1184
#define DGRID  ((NODES + 255) / 256)

extern "C" void kernel_launch(void* const* d_in, const int* in_sizes, int n_in,
                              void* d_out, int out_size) {
    const float* feat = (const float*)d_in[0];
    const float* Ws   = (const float*)d_in[1];
    const float* bs   = (const float*)d_in[2];
    const float* Wm   = (const float*)d_in[3];
    const float* bm   = (const float*)d_in[4];
    const float* Wf   = (const float*)d_in[5];
    const float* bf   = (const float*)d_in[6];
    const int*   src  = (const int*)d_in[7];
    const int*   dst  = (const int*)d_in[8];
    float* out = (float*)d_out;

    // resolve device-symbol addresses (host API, capture-safe)
    void *pA, *pB, *pY, *pCnt;
    cudaGetSymbolAddress(&pA, d_gA);
    cudaGetSymbolAddress(&pB, d_gB);
    cudaGetSymbolAddress(&pY, d_y);
    cudaGetSymbolAddress(&pCnt, d_cnt);
    float* gA = (float*)pA;
    float* gB = (float*)pB;
    float* y  = (float*)pY;

    // zero degree counters (async memset: graph-capturable)
    cudaMemsetAsync(pCnt, 0, 2 * NODES * sizeof(int));

    // build: ONE scatter pass into fixed-capacity buckets, then per-node init
    k_scatter<<<(NEDGES + 255) / 256, 256>>>(src, dst);
    k_init   <<<(NODES  + 255) / 256, 256>>>(feat);

    // layer 0 (scalar gather, fused W_start)
    k_layer0<<<L0GRID, 256>>>(Ws, bs);               // writes gA (padded)

    // 18 mid layers: dense y = g@W, then gather+epilogue
    int cur = 0;                                      // activations in gA when cur==0
    for (int k = 0; k < 18; k++) {
        const float* gin = cur ? gB : gA;
        float* gnext     = cur ? gA : gB;
        k_dense<<<DGRID, 256>>>(gin, y, Wm + k * DD * DD);
        k_agg<1, 1, 0><<<AGRID, 256>>>(y, gnext, bm + k * DD);
        cur ^= 1;
    }
    // final layer: no relu, no dout scale, packed fp32 output
    const float* gin = cur ? gB : gA;
    k_dense<<<DGRID, 256>>>(gin, y, Wf);
    k_agg<0, 0, 1><<<AGRID, 256>>>(y, out, bf);
}